// round 2
// baseline (speedup 1.0000x reference)
#include <cuda_runtime.h>

// Problem constants: B=1, H=16, S=4096, D=64, fp32, NO softmax.
// Key identity: (Q K^T) V == Q (K^T V).  K^T V is only [D x D] per head.
#define HEADS 16
#define SEQ   4096
#define DIM   64
#define NSPLIT 32
#define CHUNK (SEQ / NSPLIT)   // 128 rows of K/V per partial block

// Scratch (allocation-free rule: __device__ globals), 16B-aligned for float4.
__device__ __align__(16) float g_partial[HEADS * NSPLIT * DIM * DIM];  // 8 MB
__device__ __align__(16) float g_M[HEADS * DIM * DIM];                 // 256 KB

// ---------------------------------------------------------------------------
// Kernel 1: partial M = K_chunk^T @ V_chunk   (rank-CHUNK update of 64x64)
// grid = HEADS * NSPLIT blocks, 256 threads.
// Thread (ci,cj) owns a 4x4 tile of the 64x64 accumulator.
// ---------------------------------------------------------------------------
__global__ __launch_bounds__(256) void ktv_partial(const float* __restrict__ Kp,
                                                   const float* __restrict__ Vp) {
    const int h  = blockIdx.x / NSPLIT;
    const int sp = blockIdx.x % NSPLIT;
    const float* Kh = Kp + ((size_t)h * SEQ + (size_t)sp * CHUNK) * DIM;
    const float* Vh = Vp + ((size_t)h * SEQ + (size_t)sp * CHUNK) * DIM;

    __shared__ __align__(16) float Ks[32][DIM];   // row stride 256B -> float4-safe
    __shared__ __align__(16) float Vs[32][DIM];

    const int tid = threadIdx.x;
    const int ci = tid >> 4;   // 0..15 -> rows di = 4*ci..
    const int cj = tid & 15;   // 0..15 -> cols dj = 4*cj..

    float acc[4][4] = {};

    for (int t = 0; t < CHUNK; t += 32) {
        // cooperative load: 32 rows x 64 floats of K and V (512 float4 each)
        #pragma unroll
        for (int i = tid; i < 32 * 16; i += 256) {
            const int r  = i >> 4;
            const int c4 = (i & 15) << 2;
            *(float4*)&Ks[r][c4] = *(const float4*)&Kh[(size_t)(t + r) * DIM + c4];
            *(float4*)&Vs[r][c4] = *(const float4*)&Vh[(size_t)(t + r) * DIM + c4];
        }
        __syncthreads();

        #pragma unroll
        for (int s = 0; s < 32; s++) {
            const float4 kv = *(const float4*)&Ks[s][ci * 4];
            const float4 vv = *(const float4*)&Vs[s][cj * 4];
            const float ka[4] = {kv.x, kv.y, kv.z, kv.w};
            const float vb[4] = {vv.x, vv.y, vv.z, vv.w};
            #pragma unroll
            for (int a = 0; a < 4; a++)
                #pragma unroll
                for (int b = 0; b < 4; b++)
                    acc[a][b] += ka[a] * vb[b];
        }
        __syncthreads();
    }

    float* outp = g_partial + ((size_t)h * NSPLIT + sp) * DIM * DIM;
    #pragma unroll
    for (int a = 0; a < 4; a++) {
        float4 ov;
        ov.x = acc[a][0]; ov.y = acc[a][1]; ov.z = acc[a][2]; ov.w = acc[a][3];
        *(float4*)&outp[(ci * 4 + a) * DIM + cj * 4] = ov;
    }
}

// ---------------------------------------------------------------------------
// Kernel 2: reduce the NSPLIT partials -> g_M.  HEADS*DIM*DIM = 65536 elems.
// ---------------------------------------------------------------------------
__global__ __launch_bounds__(256) void reduce_m() {
    const int idx = blockIdx.x * 256 + threadIdx.x;
    if (idx >= HEADS * DIM * DIM) return;
    const int h = idx / (DIM * DIM);
    const int e = idx % (DIM * DIM);
    float s = 0.f;
    #pragma unroll
    for (int p = 0; p < NSPLIT; p++)
        s += g_partial[((size_t)h * NSPLIT + p) * DIM * DIM + e];
    g_M[idx] = s;
}

// ---------------------------------------------------------------------------
// Kernel 3: out = Q @ M.   grid = HEADS * (SEQ/64) blocks, 256 threads.
// Each block: 64 q-rows x 64 cols. Q tile stored TRANSPOSED in smem so the
// inner loop is two float4 LDS + 16 FFMA (same shape as kernel 1).
// Pad = +4 floats so every row start stays 16B-aligned (272B row stride).
// ---------------------------------------------------------------------------
#define QROWS 64
__global__ __launch_bounds__(256) void qm_gemm(const float* __restrict__ Qp,
                                               float* __restrict__ Op) {
    const int blocksPerHead = SEQ / QROWS;                 // 64
    const int h  = blockIdx.x / blocksPerHead;
    const int r0 = (blockIdx.x % blocksPerHead) * QROWS;

    __shared__ __align__(16) float Qt[DIM][QROWS + 4];   // transposed: Qt[k][row]
    __shared__ __align__(16) float Ms[DIM][DIM];

    const int tid = threadIdx.x;
    const float* Qh = Qp + ((size_t)h * SEQ + r0) * DIM;
    const float* Mh = g_M + (size_t)h * DIM * DIM;

    // load M (4096 floats = 1024 float4; 4 per thread)
    #pragma unroll
    for (int i = tid; i < DIM * DIM / 4; i += 256) {
        const int r  = i >> 4;
        const int c4 = (i & 15) << 2;
        *(float4*)&Ms[r][c4] = *(const float4*)&Mh[r * DIM + c4];
    }
    // load Q tile, transpose into smem (scalar stores; one-time cost)
    #pragma unroll
    for (int i = tid; i < QROWS * DIM / 4; i += 256) {
        const int r  = i >> 4;          // q-row 0..63
        const int c4 = (i & 15) << 2;   // k 0..60
        const float4 qv = *(const float4*)&Qh[(size_t)r * DIM + c4];
        Qt[c4 + 0][r] = qv.x;
        Qt[c4 + 1][r] = qv.y;
        Qt[c4 + 2][r] = qv.z;
        Qt[c4 + 3][r] = qv.w;
    }
    __syncthreads();

    const int ci = tid >> 4;   // 0..15 -> q rows 4*ci..
    const int cj = tid & 15;   // 0..15 -> out cols 4*cj..

    float acc[4][4] = {};
    #pragma unroll
    for (int k = 0; k < DIM; k++) {
        const float4 qv = *(const float4*)&Qt[k][ci * 4];   // 16B-aligned: (68*k+4*ci)*4 % 16 == 0
        const float4 mv = *(const float4*)&Ms[k][cj * 4];
        const float qa[4] = {qv.x, qv.y, qv.z, qv.w};
        const float mb[4] = {mv.x, mv.y, mv.z, mv.w};
        #pragma unroll
        for (int a = 0; a < 4; a++)
            #pragma unroll
            for (int b = 0; b < 4; b++)
                acc[a][b] += qa[a] * mb[b];
    }

    float* Oh = Op + ((size_t)h * SEQ + r0) * DIM;
    #pragma unroll
    for (int a = 0; a < 4; a++) {
        float4 ov;
        ov.x = acc[a][0]; ov.y = acc[a][1]; ov.z = acc[a][2]; ov.w = acc[a][3];
        *(float4*)&Oh[(size_t)(ci * 4 + a) * DIM + cj * 4] = ov;
    }
}

// ---------------------------------------------------------------------------
extern "C" void kernel_launch(void* const* d_in, const int* in_sizes, int n_in,
                              void* d_out, int out_size) {
    const float* q = (const float*)d_in[0];
    const float* k = (const float*)d_in[1];
    const float* v = (const float*)d_in[2];
    float* out = (float*)d_out;

    ktv_partial<<<HEADS * NSPLIT, 256>>>(k, v);
    reduce_m<<<(HEADS * DIM * DIM + 255) / 256, 256>>>();
    qm_gemm<<<HEADS * (SEQ / QROWS), 256>>>(q, out);
}